// round 1
// baseline (speedup 1.0000x reference)
#include <cuda_runtime.h>

#define BB 4
#define FF 16
#define NP 196
#define DIM 512
#define HH 8
#define DH 64
#define NTOT 3137            // 1 + FF*NP
#define MROWS (BB*NTOT)      // 12548
#define BHN (BB*HH)          // 32
#define QCOLS (3*HH*DH)      // 1536
#define SCALE 0.125f

// Scratch (device globals; no dynamic allocation allowed)
static __device__ float d_Q [(size_t)BHN*NTOT*DH];
static __device__ float d_Kb[(size_t)BHN*NTOT*DH];
static __device__ float d_Vb[(size_t)BHN*NTOT*DH];
static __device__ float d_O [(size_t)MROWS*DIM];

// ---- packed fp32x2 helpers (Blackwell dual-fp32 pipe, PTX-only) ----
__device__ __forceinline__ unsigned long long pack2(float lo, float hi) {
    unsigned long long r;
    asm("mov.b64 %0, {%1, %2};" : "=l"(r) : "f"(lo), "f"(hi));
    return r;
}
__device__ __forceinline__ void unpack2(unsigned long long v, float& lo, float& hi) {
    asm("mov.b64 {%0, %1}, %2;" : "=f"(lo), "=f"(hi) : "l"(v));
}
__device__ __forceinline__ unsigned long long ffma2(unsigned long long a, unsigned long long b, unsigned long long c) {
    unsigned long long d;
    asm("fma.rn.f32x2 %0, %1, %2, %3;" : "=l"(d) : "l"(a), "l"(b), "l"(c));
    return d;
}
__device__ __forceinline__ unsigned long long fmul2(unsigned long long a, unsigned long long b) {
    unsigned long long d;
    asm("mul.rn.f32x2 %0, %1, %2;" : "=l"(d) : "l"(a), "l"(b));
    return d;
}

// ============================================================================
// Tiled fp32 GEMM, 128x128 tile, BK=16, 256 threads, 8x8 per thread (f32x2).
// PROJ=false: A = x, B = W_qkv, epilogue scatters into d_Q/d_Kb/d_Vb (scaled Q).
// PROJ=true : A = d_O, B = W_out, epilogue adds bias and writes C.
// ============================================================================
template<int NC, bool PROJ>
__global__ __launch_bounds__(256) void gemm_kernel(
    const float* __restrict__ A, const float* __restrict__ Bw,
    const float* __restrict__ bias, float* __restrict__ C)
{
    __shared__ __align__(16) unsigned long long As2[16][128]; // duplicated pairs
    __shared__ __align__(16) float Bs[16][128];

    const int tid  = threadIdx.x;
    const int tx   = tid & 15;
    const int ty   = tid >> 4;
    const int row0 = blockIdx.y * 128;
    const int col0 = blockIdx.x * 128;
    const float* __restrict__ Ap = PROJ ? (const float*)d_O : A;

    unsigned long long acc[8][4];
    #pragma unroll
    for (int i = 0; i < 8; i++)
        #pragma unroll
        for (int j = 0; j < 4; j++) acc[i][j] = 0ULL;

    for (int k0 = 0; k0 < DIM; k0 += 16) {
        #pragma unroll
        for (int i = 0; i < 8; i++) {
            int idx = tid + i * 256;
            int m = idx >> 4, kk = idx & 15;
            int row = row0 + m;
            float v = (row < MROWS) ? Ap[(size_t)row * DIM + k0 + kk] : 0.0f;
            As2[kk][m] = pack2(v, v);
        }
        #pragma unroll
        for (int i = 0; i < 8; i++) {
            int idx = tid + i * 256;
            int kk = idx >> 7, n = idx & 127;
            Bs[kk][n] = Bw[(size_t)(k0 + kk) * NC + col0 + n];
        }
        __syncthreads();
        #pragma unroll
        for (int kk = 0; kk < 16; kk++) {
            unsigned long long a2[8], b2[4];
            #pragma unroll
            for (int i = 0; i < 8; i++) a2[i] = As2[kk][ty * 8 + i];
            const unsigned long long* bp =
                reinterpret_cast<const unsigned long long*>(&Bs[kk][tx * 8]);
            #pragma unroll
            for (int j = 0; j < 4; j++) b2[j] = bp[j];
            #pragma unroll
            for (int i = 0; i < 8; i++)
                #pragma unroll
                for (int j = 0; j < 4; j++)
                    acc[i][j] = ffma2(a2[i], b2[j], acc[i][j]);
        }
        __syncthreads();
    }

    #pragma unroll
    for (int i = 0; i < 8; i++) {
        int row = row0 + ty * 8 + i;
        if (row >= MROWS) break;
        int b = row / NTOT;
        int n = row - b * NTOT;
        #pragma unroll
        for (int j = 0; j < 4; j++) {
            float lo, hi;
            unpack2(acc[i][j], lo, hi);
            int c0 = col0 + tx * 8 + 2 * j;
            if (PROJ) {
                C[(size_t)row * NC + c0    ] = lo + bias[c0];
                C[(size_t)row * NC + c0 + 1] = hi + bias[c0 + 1];
            } else {
                #pragma unroll
                for (int e = 0; e < 2; e++) {
                    int c = c0 + e;
                    float v = e ? hi : lo;
                    int which = c >> 9;          // 0=q, 1=k, 2=v
                    int rem = c & 511;
                    int h = rem >> 6, d = rem & 63;
                    size_t off = (((size_t)b * HH + h) * NTOT + n) * DH + d;
                    if      (which == 0) d_Q [off] = v * SCALE;
                    else if (which == 1) d_Kb[off] = v;
                    else                 d_Vb[off] = v;
                }
            }
        }
    }
}

// ============================================================================
// cls-token attention: one block per (b,h). cls_q attends to all 3137 keys.
// ============================================================================
__global__ __launch_bounds__(256) void cls_attn_kernel()
{
    __shared__ float s[NTOT];
    __shared__ __align__(16) float qv[DH];
    __shared__ float redA[8];
    __shared__ float outp[4][64];

    const int bh  = blockIdx.x;
    const int tid = threadIdx.x;
    const float* __restrict__ Kp = d_Kb + (size_t)bh * NTOT * DH;
    const float* __restrict__ Vp = d_Vb + (size_t)bh * NTOT * DH;

    if (tid < DH) qv[tid] = d_Q[(size_t)bh * NTOT * DH + tid]; // cls_q (pre-scaled)
    __syncthreads();

    const unsigned long long* q2 = reinterpret_cast<const unsigned long long*>(qv);
    float lmax = -1e30f;
    for (int j = tid; j < NTOT; j += 256) {
        const unsigned long long* kr =
            reinterpret_cast<const unsigned long long*>(Kp + (size_t)j * DH);
        unsigned long long dacc = 0ULL;
        #pragma unroll
        for (int t = 0; t < 32; t++) dacc = ffma2(q2[t], kr[t], dacc);
        float lo, hi; unpack2(dacc, lo, hi);
        float sv = lo + hi;
        s[j] = sv;
        lmax = fmaxf(lmax, sv);
    }
    #pragma unroll
    for (int o = 16; o; o >>= 1) lmax = fmaxf(lmax, __shfl_xor_sync(0xffffffffu, lmax, o));
    if ((tid & 31) == 0) redA[tid >> 5] = lmax;
    __syncthreads();
    float m = fmaxf(fmaxf(fmaxf(redA[0], redA[1]), fmaxf(redA[2], redA[3])),
                    fmaxf(fmaxf(redA[4], redA[5]), fmaxf(redA[6], redA[7])));
    __syncthreads();   // everyone has read redA before it is reused

    float lsum = 0.f;
    for (int j = tid; j < NTOT; j += 256) {
        float p = __expf(s[j] - m);
        s[j] = p;
        lsum += p;
    }
    #pragma unroll
    for (int o = 16; o; o >>= 1) lsum += __shfl_xor_sync(0xffffffffu, lsum, o);
    if ((tid & 31) == 0) redA[tid >> 5] = lsum;
    __syncthreads();
    float Z = redA[0] + redA[1] + redA[2] + redA[3] +
              redA[4] + redA[5] + redA[6] + redA[7];

    // PV: 4 groups of 64 threads; thread (g,d) sums j = g, g+4, ...
    int d = tid & 63;
    int g = tid >> 6;
    float acc = 0.f;
    for (int j = g; j < NTOT; j += 4)
        acc += s[j] * Vp[(size_t)j * DH + d];
    outp[g][d] = acc;
    __syncthreads();
    if (tid < 64) {
        float o = (outp[0][tid] + outp[1][tid] + outp[2][tid] + outp[3][tid]) / Z;
        int b = bh / HH, h = bh - b * HH;
        d_O[((size_t)b * NTOT + 0) * DIM + h * DH + tid] = o;
    }
}

// ============================================================================
// Local attention: one block per (b,h,f). 196 queries, 197 keys (cls + 196).
// K/V tile in dynamic SMEM (101 KB); one thread per query, online softmax.
// SMEM reads of k/v rows are uniform across the warp -> broadcast, no conflicts.
// ============================================================================
__global__ __launch_bounds__(256) void local_attn_kernel()
{
    extern __shared__ __align__(16) float sm[];
    float* ks = sm;                  // 197*64
    float* vs = sm + 197 * 64;       // 197*64

    const int bhf = blockIdx.x;
    const int bh  = bhf >> 4;
    const int f   = bhf & 15;
    const size_t base = (size_t)bh * NTOT * DH;
    const int tid = threadIdx.x;

    const int TOTAL = 197 * 64;
    for (int i = tid; i < TOTAL; i += 256) {
        int r = i >> 6, d = i & 63;
        int n = (r == 0) ? 0 : (1 + f * NP + r - 1);
        ks[i] = d_Kb[base + (size_t)n * DH + d];
        vs[i] = d_Vb[base + (size_t)n * DH + d];
    }
    __syncthreads();

    if (tid < NP) {
        int nq = 1 + f * NP + tid;
        unsigned long long q2[32];
        const unsigned long long* qg =
            reinterpret_cast<const unsigned long long*>(d_Q + base + (size_t)nq * DH);
        #pragma unroll
        for (int t = 0; t < 32; t++) q2[t] = qg[t];

        const unsigned long long* k2 = reinterpret_cast<const unsigned long long*>(ks);
        const unsigned long long* v2 = reinterpret_cast<const unsigned long long*>(vs);

        float m = -1e30f, l = 0.f;
        unsigned long long acc[32];
        #pragma unroll
        for (int t = 0; t < 32; t++) acc[t] = 0ULL;

        for (int j = 0; j < 197; j++) {
            unsigned long long dacc = 0ULL;
            #pragma unroll
            for (int t = 0; t < 32; t++) dacc = ffma2(q2[t], k2[j * 32 + t], dacc);
            float lo, hi; unpack2(dacc, lo, hi);
            float sv = lo + hi;
            if (sv > m) {
                float c = __expf(m - sv);     // exp(-inf)=0 on first hit
                l *= c;
                unsigned long long c2 = pack2(c, c);
                #pragma unroll
                for (int t = 0; t < 32; t++) acc[t] = fmul2(acc[t], c2);
                m = sv;
            }
            float p = __expf(sv - m);
            l += p;
            unsigned long long p2 = pack2(p, p);
            #pragma unroll
            for (int t = 0; t < 32; t++) acc[t] = ffma2(p2, v2[j * 32 + t], acc[t]);
        }
        float inv = 1.0f / l;
        int b = bh / HH, h = bh - b * HH;
        float* op = d_O + ((size_t)b * NTOT + nq) * DIM + h * DH;
        #pragma unroll
        for (int t = 0; t < 32; t++) {
            float lo, hi; unpack2(acc[t], lo, hi);
            op[2 * t]     = lo * inv;
            op[2 * t + 1] = hi * inv;
        }
    }
}

// ============================================================================
extern "C" void kernel_launch(void* const* d_in, const int* in_sizes, int n_in,
                              void* d_out, int out_size)
{
    const float* x    = (const float*)d_in[0];
    const float* Wqkv = (const float*)d_in[1];
    const float* Wout = (const float*)d_in[2];
    const float* bout = (const float*)d_in[3];
    float* out = (float*)d_out;

    const int LOC_SMEM = 2 * 197 * 64 * (int)sizeof(float);   // 100864 B
    cudaFuncSetAttribute(local_attn_kernel,
                         cudaFuncAttributeMaxDynamicSharedMemorySize, LOC_SMEM);

    dim3 blk(256);
    // 1) QKV GEMM + scatter (scaled Q)
    gemm_kernel<QCOLS, false><<<dim3(QCOLS / 128, (MROWS + 127) / 128), blk>>>(
        x, Wqkv, nullptr, nullptr);
    // 2) cls attention (independent of 3, same stream serializes)
    cls_attn_kernel<<<BHN, blk>>>();
    // 3) local attention
    local_attn_kernel<<<BB * HH * FF, blk, LOC_SMEM>>>();
    // 4) output projection + bias
    gemm_kernel<DIM, true><<<dim3(DIM / 128, (MROWS + 127) / 128), blk>>>(
        nullptr, Wout, bout, out);
}

// round 10
// speedup vs baseline: 1.9963x; 1.9963x over previous
#include <cuda_runtime.h>
#include <cuda_bf16.h>
#include <cstdint>

#define BB 4
#define FF 16
#define NP 196
#define DIM 512
#define HH 8
#define DH 64
#define NTOT 3137            // 1 + FF*NP
#define MROWS (BB*NTOT)      // 12548
#define BHN (BB*HH)          // 32
#define QCOLS (3*HH*DH)      // 1536
#define SCALE 0.125f

// ---------------- scratch (device globals; no dynamic allocation) ----------
static __device__ float d_Q [(size_t)BHN*NTOT*DH];
static __device__ float d_Kb[(size_t)BHN*NTOT*DH];
static __device__ float d_Vb[(size_t)BHN*NTOT*DH];
static __device__ float d_O [(size_t)MROWS*DIM];
static __device__ __nv_bfloat16 d_WqkvT_h[(size_t)QCOLS*DIM];
static __device__ __nv_bfloat16 d_WqkvT_l[(size_t)QCOLS*DIM];
static __device__ __nv_bfloat16 d_WoutT_h[(size_t)DIM*DIM];
static __device__ __nv_bfloat16 d_WoutT_l[(size_t)DIM*DIM];

// ---------------- helpers ---------------------------------------------------
__device__ __forceinline__ void mma_bf16(float* c, const uint32_t* a, const uint32_t* b) {
    asm volatile("mma.sync.aligned.m16n8k16.row.col.f32.bf16.bf16.f32 "
                 "{%0,%1,%2,%3}, {%4,%5,%6,%7}, {%8,%9}, {%0,%1,%2,%3};"
                 : "+f"(c[0]), "+f"(c[1]), "+f"(c[2]), "+f"(c[3])
                 : "r"(a[0]), "r"(a[1]), "r"(a[2]), "r"(a[3]), "r"(b[0]), "r"(b[1]));
}
__device__ __forceinline__ uint32_t pbf2(__nv_bfloat16 a, __nv_bfloat16 b) {
    __nv_bfloat162 t = __halves2bfloat162(a, b);
    return *reinterpret_cast<uint32_t*>(&t);
}

// ---- packed fp32x2 helpers for attention ----------------------------------
__device__ __forceinline__ unsigned long long pack2(float lo, float hi) {
    unsigned long long r;
    asm("mov.b64 %0, {%1, %2};" : "=l"(r) : "f"(lo), "f"(hi));
    return r;
}
__device__ __forceinline__ void unpack2(unsigned long long v, float& lo, float& hi) {
    asm("mov.b64 {%0, %1}, %2;" : "=f"(lo), "=f"(hi) : "l"(v));
}
__device__ __forceinline__ unsigned long long ffma2(unsigned long long a, unsigned long long b, unsigned long long c) {
    unsigned long long d;
    asm("fma.rn.f32x2 %0, %1, %2, %3;" : "=l"(d) : "l"(a), "l"(b), "l"(c));
    return d;
}
__device__ __forceinline__ unsigned long long fmul2(unsigned long long a, unsigned long long b) {
    unsigned long long d;
    asm("mul.rn.f32x2 %0, %1, %2;" : "=l"(d) : "l"(a), "l"(b));
    return d;
}

// ============================================================================
// Weight preprocessing: W [K=512][C] -> WT hi/lo bf16 [C][512]
// ============================================================================
template<bool QKV>
__global__ void transpose_split(const float* __restrict__ W) {
    const int C = QKV ? QCOLS : DIM;
    int idx = blockIdx.x * blockDim.x + threadIdx.x;
    if (idx < C * DIM) {
        int c = idx >> 9, k = idx & 511;
        float v = W[(size_t)k * C + c];
        __nv_bfloat16 h = __float2bfloat16_rn(v);
        __nv_bfloat16 l = __float2bfloat16_rn(v - __bfloat162float(h));
        if (QKV) { d_WqkvT_h[idx] = h; d_WqkvT_l[idx] = l; }
        else     { d_WoutT_h[idx] = h; d_WoutT_l[idx] = l; }
    }
}

// ============================================================================
// HMMA bf16 GEMM with 2-term compensation:  D = Ah*Bh + Ah*Bl + Al*Bh
// 128x128 tile, BK=32, 256 threads (8 warps, 2x4 grid, 64x32 per warp).
// Fragments loaded with explicit per-thread LDS (documented thread mapping).
// NOTE: PROJ's A operand (d_O) is resolved IN DEVICE CODE — passing the
// __device__ symbol from host silently binds the host shadow (ATS reads zeros).
// ============================================================================
#define APAD 40                     // bf16 elems per smem row (32 + 8 pad)
#define SM_AH 0
#define SM_AL (128*APAD)
#define SM_BH (2*128*APAD)
#define SM_BL (3*128*APAD)
#define GEMM_DSMEM (128*132*4)      // 67584 (epilogue is the max user)

template<int NC, bool PROJ>
__global__ __launch_bounds__(256) void gemm_tc(
    const float* __restrict__ A, const float* __restrict__ bias, float* __restrict__ C)
{
    extern __shared__ __align__(16) char dyn[];
    __nv_bfloat16* sm16 = reinterpret_cast<__nv_bfloat16*>(dyn);

    const int tid  = threadIdx.x;
    const int wid  = tid >> 5;
    const int lane = tid & 31;
    const int wr   = wid >> 2;          // 0..1
    const int wc   = wid & 3;           // 0..3
    const int g    = lane >> 2;         // 0..7  (fragment group)
    const int tg   = lane & 3;          // 0..3  (thread-in-group)
    const int row0 = blockIdx.y * 128;
    const int col0 = blockIdx.x * 128;

    // Resolve operands in DEVICE code (device-symbol addresses valid here).
    const float* __restrict__ Ap = PROJ ? (const float*)d_O : A;
    const __nv_bfloat16* __restrict__ BTh = PROJ ? d_WoutT_h : d_WqkvT_h;
    const __nv_bfloat16* __restrict__ BTl = PROJ ? d_WoutT_l : d_WqkvT_l;

    float acc[4][4][4];
    #pragma unroll
    for (int i = 0; i < 4; i++)
        #pragma unroll
        for (int j = 0; j < 4; j++)
            #pragma unroll
            for (int e = 0; e < 4; e++) acc[i][j][e] = 0.f;

    // loader mapping: thread t -> row lr, k-half lh (16 elems each)
    const int lr = tid >> 1;
    const int lh = tid & 1;
    const int grA = row0 + lr;
    const bool okA = (grA < MROWS);
    const size_t aRow = (size_t)grA * DIM + lh * 16;
    const size_t bRow = (size_t)(col0 + lr) * DIM + lh * 16;

    float4 stA[4];
    uint4  stBh[2], stBl[2];

    auto load_regs = [&](int cc) {
        const int k0 = cc * 32;
        if (okA) {
            #pragma unroll
            for (int i = 0; i < 4; i++)
                stA[i] = *reinterpret_cast<const float4*>(&Ap[aRow + k0 + i * 4]);
        } else {
            #pragma unroll
            for (int i = 0; i < 4; i++) stA[i] = make_float4(0.f, 0.f, 0.f, 0.f);
        }
        stBh[0] = *reinterpret_cast<const uint4*>(&BTh[bRow + k0]);
        stBh[1] = *reinterpret_cast<const uint4*>(&BTh[bRow + k0 + 8]);
        stBl[0] = *reinterpret_cast<const uint4*>(&BTl[bRow + k0]);
        stBl[1] = *reinterpret_cast<const uint4*>(&BTl[bRow + k0 + 8]);
    };

    auto store_smem = [&]() {
        uint32_t hw[8], lw[8];
        #pragma unroll
        for (int i = 0; i < 4; i++) {
            float4 v = stA[i];
            __nv_bfloat16 h0 = __float2bfloat16_rn(v.x);
            __nv_bfloat16 h1 = __float2bfloat16_rn(v.y);
            __nv_bfloat16 h2 = __float2bfloat16_rn(v.z);
            __nv_bfloat16 h3 = __float2bfloat16_rn(v.w);
            hw[2*i]   = pbf2(h0, h1);
            hw[2*i+1] = pbf2(h2, h3);
            lw[2*i]   = pbf2(__float2bfloat16_rn(v.x - __bfloat162float(h0)),
                             __float2bfloat16_rn(v.y - __bfloat162float(h1)));
            lw[2*i+1] = pbf2(__float2bfloat16_rn(v.z - __bfloat162float(h2)),
                             __float2bfloat16_rn(v.w - __bfloat162float(h3)));
        }
        const int ao = lr * APAD + lh * 16;
        *reinterpret_cast<uint4*>(&sm16[SM_AH + ao])     = make_uint4(hw[0],hw[1],hw[2],hw[3]);
        *reinterpret_cast<uint4*>(&sm16[SM_AH + ao + 8]) = make_uint4(hw[4],hw[5],hw[6],hw[7]);
        *reinterpret_cast<uint4*>(&sm16[SM_AL + ao])     = make_uint4(lw[0],lw[1],lw[2],lw[3]);
        *reinterpret_cast<uint4*>(&sm16[SM_AL + ao + 8]) = make_uint4(lw[4],lw[5],lw[6],lw[7]);
        *reinterpret_cast<uint4*>(&sm16[SM_BH + ao])     = stBh[0];
        *reinterpret_cast<uint4*>(&sm16[SM_BH + ao + 8]) = stBh[1];
        *reinterpret_cast<uint4*>(&sm16[SM_BL + ao])     = stBl[0];
        *reinterpret_cast<uint4*>(&sm16[SM_BL + ao + 8]) = stBl[1];
    };

    // Explicit fragment loads per documented mma.m16n8k16 thread mapping:
    //   a0 = A[m+g][k+2tg]  a1 = A[m+8+g][k+2tg]  a2 = a0 col+8  a3 = a1 col+8
    //   b0 = B[n+g][k+2tg]  b1 = b0 col+8         (B stored [n][k])
    auto compute = [&]() {
        #pragma unroll
        for (int ks = 0; ks < 2; ks++) {
            const int kc = ks * 16 + 2 * tg;
            uint32_t bh[4][2], bl[4][2];
            #pragma unroll
            for (int nt = 0; nt < 4; nt++) {
                const int nrow = (wc * 32 + nt * 8 + g) * APAD + kc;
                bh[nt][0] = *reinterpret_cast<const uint32_t*>(&sm16[SM_BH + nrow]);
                bh[nt][1] = *reinterpret_cast<const uint32_t*>(&sm16[SM_BH + nrow + 8]);
                bl[nt][0] = *reinterpret_cast<const uint32_t*>(&sm16[SM_BL + nrow]);
                bl[nt][1] = *reinterpret_cast<const uint32_t*>(&sm16[SM_BL + nrow + 8]);
            }
            #pragma unroll
            for (int mt = 0; mt < 4; mt++) {
                const int arow = (wr * 64 + mt * 16 + g) * APAD + kc;
                uint32_t a[4];
                a[0] = *reinterpret_cast<const uint32_t*>(&sm16[SM_AH + arow]);
                a[1] = *reinterpret_cast<const uint32_t*>(&sm16[SM_AH + arow + 8 * APAD]);
                a[2] = *reinterpret_cast<const uint32_t*>(&sm16[SM_AH + arow + 8]);
                a[3] = *reinterpret_cast<const uint32_t*>(&sm16[SM_AH + arow + 8 * APAD + 8]);
                #pragma unroll
                for (int nt = 0; nt < 4; nt++) mma_bf16(acc[mt][nt], a, bh[nt]);
                #pragma unroll
                for (int nt = 0; nt < 4; nt++) mma_bf16(acc[mt][nt], a, bl[nt]);
            }
            #pragma unroll
            for (int mt = 0; mt < 4; mt++) {
                const int arow = (wr * 64 + mt * 16 + g) * APAD + kc;
                uint32_t a[4];
                a[0] = *reinterpret_cast<const uint32_t*>(&sm16[SM_AL + arow]);
                a[1] = *reinterpret_cast<const uint32_t*>(&sm16[SM_AL + arow + 8 * APAD]);
                a[2] = *reinterpret_cast<const uint32_t*>(&sm16[SM_AL + arow + 8]);
                a[3] = *reinterpret_cast<const uint32_t*>(&sm16[SM_AL + arow + 8 * APAD + 8]);
                #pragma unroll
                for (int nt = 0; nt < 4; nt++) mma_bf16(acc[mt][nt], a, bh[nt]);
            }
        }
    };

    load_regs(0);
    store_smem();
    __syncthreads();
    #pragma unroll 1
    for (int cc = 0; cc < 16; cc++) {
        if (cc < 15) load_regs(cc + 1);
        compute();
        __syncthreads();
        if (cc < 15) { store_smem(); __syncthreads(); }
    }

    // ---- epilogue: fragments -> smem (stride 132) -> coalesced GMEM ----
    // C fragment: c0,c1 at (g, 2tg), c2,c3 at (g+8, 2tg)
    float* smemf = reinterpret_cast<float*>(dyn);
    #pragma unroll
    for (int mt = 0; mt < 4; mt++)
        #pragma unroll
        for (int nt = 0; nt < 4; nt++) {
            int r = wr * 64 + mt * 16 + g;
            int c = wc * 32 + nt * 8 + 2 * tg;
            *reinterpret_cast<float2*>(&smemf[r * 132 + c]) =
                make_float2(acc[mt][nt][0], acc[mt][nt][1]);
            *reinterpret_cast<float2*>(&smemf[(r + 8) * 132 + c]) =
                make_float2(acc[mt][nt][2], acc[mt][nt][3]);
        }
    __syncthreads();

    if (PROJ) {
        float4 bv = *reinterpret_cast<const float4*>(&bias[col0 + lane * 4]);
        #pragma unroll 4
        for (int it = 0; it < 16; it++) {
            int row = it * 8 + wid;
            int gr = row0 + row;
            if (gr < MROWS) {
                float4 v = *reinterpret_cast<const float4*>(&smemf[row * 132 + lane * 4]);
                v.x += bv.x; v.y += bv.y; v.z += bv.z; v.w += bv.w;
                *reinterpret_cast<float4*>(&C[(size_t)gr * DIM + col0 + lane * 4]) = v;
            }
        }
    } else {
        #pragma unroll 2
        for (int it = 0; it < 16; it++) {
            int row = it * 8 + wid;
            int gr = row0 + row;
            if (gr < MROWS) {
                int bb = gr / NTOT;
                int n  = gr - bb * NTOT;
                #pragma unroll
                for (int gg = 0; gg < 2; gg++) {
                    float2 v = *reinterpret_cast<const float2*>(
                        &smemf[row * 132 + gg * 64 + lane * 2]);
                    int cb = col0 + gg * 64;
                    int which = cb >> 9;
                    int h = (cb >> 6) & 7;
                    float* dst;
                    if (which == 0) { v.x *= SCALE; v.y *= SCALE; dst = d_Q; }
                    else if (which == 1) dst = d_Kb;
                    else                 dst = d_Vb;
                    *reinterpret_cast<float2*>(
                        &dst[(((size_t)bb * HH + h) * NTOT + n) * DH + lane * 2]) = v;
                }
            }
        }
    }
}

// ============================================================================
// cls-token attention: one block per (b,h). cls_q attends to all 3137 keys.
// ============================================================================
__global__ __launch_bounds__(256) void cls_attn_kernel()
{
    __shared__ float s[NTOT];
    __shared__ __align__(16) float qv[DH];
    __shared__ float redA[8];
    __shared__ float outp[4][64];

    const int bh  = blockIdx.x;
    const int tid = threadIdx.x;
    const float* __restrict__ Kp = d_Kb + (size_t)bh * NTOT * DH;
    const float* __restrict__ Vp = d_Vb + (size_t)bh * NTOT * DH;

    if (tid < DH) qv[tid] = d_Q[(size_t)bh * NTOT * DH + tid];
    __syncthreads();

    const unsigned long long* q2 = reinterpret_cast<const unsigned long long*>(qv);
    float lmax = -1e30f;
    for (int j = tid; j < NTOT; j += 256) {
        const unsigned long long* kr =
            reinterpret_cast<const unsigned long long*>(Kp + (size_t)j * DH);
        unsigned long long dacc = 0ULL;
        #pragma unroll
        for (int t = 0; t < 32; t++) dacc = ffma2(q2[t], kr[t], dacc);
        float lo, hi; unpack2(dacc, lo, hi);
        float sv = lo + hi;
        s[j] = sv;
        lmax = fmaxf(lmax, sv);
    }
    #pragma unroll
    for (int o = 16; o; o >>= 1) lmax = fmaxf(lmax, __shfl_xor_sync(0xffffffffu, lmax, o));
    if ((tid & 31) == 0) redA[tid >> 5] = lmax;
    __syncthreads();
    float m = fmaxf(fmaxf(fmaxf(redA[0], redA[1]), fmaxf(redA[2], redA[3])),
                    fmaxf(fmaxf(redA[4], redA[5]), fmaxf(redA[6], redA[7])));
    __syncthreads();

    float lsum = 0.f;
    for (int j = tid; j < NTOT; j += 256) {
        float p = __expf(s[j] - m);
        s[j] = p;
        lsum += p;
    }
    #pragma unroll
    for (int o = 16; o; o >>= 1) lsum += __shfl_xor_sync(0xffffffffu, lsum, o);
    if ((tid & 31) == 0) redA[tid >> 5] = lsum;
    __syncthreads();
    float Z = redA[0] + redA[1] + redA[2] + redA[3] +
              redA[4] + redA[5] + redA[6] + redA[7];

    int d = tid & 63;
    int g = tid >> 6;
    float acc = 0.f;
    for (int j = g; j < NTOT; j += 4)
        acc += s[j] * Vp[(size_t)j * DH + d];
    outp[g][d] = acc;
    __syncthreads();
    if (tid < 64) {
        float o = (outp[0][tid] + outp[1][tid] + outp[2][tid] + outp[3][tid]) / Z;
        int b = bh / HH, h = bh - b * HH;
        d_O[((size_t)b * NTOT + 0) * DIM + h * DH + tid] = o;
    }
}

// ============================================================================
// Local attention: one block per (b,h,f). 196 queries, 197 keys (cls + 196).
// ============================================================================
__global__ __launch_bounds__(256) void local_attn_kernel()
{
    extern __shared__ __align__(16) float sm[];
    float* ks = sm;                  // 197*64
    float* vs = sm + 197 * 64;       // 197*64

    const int bhf = blockIdx.x;
    const int bh  = bhf >> 4;
    const int f   = bhf & 15;
    const size_t base = (size_t)bh * NTOT * DH;
    const int tid = threadIdx.x;

    const int TOTAL = 197 * 64;
    for (int i = tid; i < TOTAL; i += 256) {
        int r = i >> 6, d = i & 63;
        int n = (r == 0) ? 0 : (1 + f * NP + r - 1);
        ks[i] = d_Kb[base + (size_t)n * DH + d];
        vs[i] = d_Vb[base + (size_t)n * DH + d];
    }
    __syncthreads();

    if (tid < NP) {
        int nq = 1 + f * NP + tid;
        unsigned long long q2[32];
        const unsigned long long* qg =
            reinterpret_cast<const unsigned long long*>(d_Q + base + (size_t)nq * DH);
        #pragma unroll
        for (int t = 0; t < 32; t++) q2[t] = qg[t];

        const unsigned long long* k2 = reinterpret_cast<const unsigned long long*>(ks);
        const unsigned long long* v2 = reinterpret_cast<const unsigned long long*>(vs);

        float m = -1e30f, l = 0.f;
        unsigned long long acc[32];
        #pragma unroll
        for (int t = 0; t < 32; t++) acc[t] = 0ULL;

        for (int j = 0; j < 197; j++) {
            unsigned long long dacc = 0ULL;
            #pragma unroll
            for (int t = 0; t < 32; t++) dacc = ffma2(q2[t], k2[j * 32 + t], dacc);
            float lo, hi; unpack2(dacc, lo, hi);
            float sv = lo + hi;
            if (sv > m) {
                float c = __expf(m - sv);
                l *= c;
                unsigned long long c2 = pack2(c, c);
                #pragma unroll
                for (int t = 0; t < 32; t++) acc[t] = fmul2(acc[t], c2);
                m = sv;
            }
            float p = __expf(sv - m);
            l += p;
            unsigned long long p2 = pack2(p, p);
            #pragma unroll
            for (int t = 0; t < 32; t++) acc[t] = ffma2(p2, v2[j * 32 + t], acc[t]);
        }
        float inv = 1.0f / l;
        int b = bh / HH, h = bh - b * HH;
        float* op = d_O + ((size_t)b * NTOT + nq) * DIM + h * DH;
        #pragma unroll
        for (int t = 0; t < 32; t++) {
            float lo, hi; unpack2(acc[t], lo, hi);
            op[2 * t]     = lo * inv;
            op[2 * t + 1] = hi * inv;
        }
    }
}

// ============================================================================
extern "C" void kernel_launch(void* const* d_in, const int* in_sizes, int n_in,
                              void* d_out, int out_size)
{
    const float* x    = (const float*)d_in[0];
    const float* Wqkv = (const float*)d_in[1];
    const float* Wout = (const float*)d_in[2];
    const float* bout = (const float*)d_in[3];
    float* out = (float*)d_out;

    const int LOC_SMEM = 2 * 197 * 64 * (int)sizeof(float);   // 100864 B
    cudaFuncSetAttribute(local_attn_kernel,
                         cudaFuncAttributeMaxDynamicSharedMemorySize, LOC_SMEM);
    cudaFuncSetAttribute(gemm_tc<QCOLS, false>,
                         cudaFuncAttributeMaxDynamicSharedMemorySize, GEMM_DSMEM);
    cudaFuncSetAttribute(gemm_tc<DIM, true>,
                         cudaFuncAttributeMaxDynamicSharedMemorySize, GEMM_DSMEM);

    // 0) pre-split + transpose weights (bf16 hi/lo)
    transpose_split<true ><<<(QCOLS * DIM + 255) / 256, 256>>>(Wqkv);
    transpose_split<false><<<(DIM * DIM + 255) / 256, 256>>>(Wout);

    // 1) QKV GEMM (HMMA) + scatter to Q/K/V (scaled Q)
    gemm_tc<QCOLS, false><<<dim3(QCOLS / 128, (MROWS + 127) / 128), 256, GEMM_DSMEM>>>(
        x, nullptr, nullptr);

    // 2) cls attention
    cls_attn_kernel<<<BHN, 256>>>();

    // 3) local attention
    local_attn_kernel<<<BB * HH * FF, 256, LOC_SMEM>>>();

    // 4) output projection (HMMA) + bias — A resolved in device code (d_O)
    gemm_tc<DIM, true><<<dim3(DIM / 128, (MROWS + 127) / 128), 256, GEMM_DSMEM>>>(
        nullptr, bout, out);
}

// round 11
// speedup vs baseline: 2.2738x; 1.1390x over previous
#include <cuda_runtime.h>
#include <cuda_bf16.h>
#include <cstdint>

#define BB 4
#define FF 16
#define NP 196
#define DIM 512
#define HH 8
#define DH 64
#define NTOT 3137            // 1 + FF*NP
#define MROWS (BB*NTOT)      // 12548
#define BHN (BB*HH)          // 32
#define QCOLS (3*HH*DH)      // 1536
#define SCALE 0.125f
#define CLS_CHUNKS 16
#define CLS_KEYS 197         // keys per chunk (last chunk: 182)

// ---------------- scratch (device globals; no dynamic allocation) ----------
static __device__ float d_Q [(size_t)BHN*NTOT*DH];
static __device__ float d_Kb[(size_t)BHN*NTOT*DH];
static __device__ float d_Vb[(size_t)BHN*NTOT*DH];
static __device__ float d_O [(size_t)MROWS*DIM];
static __device__ float d_clsP[(size_t)BHN*CLS_CHUNKS*66];   // m, l, acc[64]
static __device__ __nv_bfloat16 d_WqkvT_h[(size_t)QCOLS*DIM];
static __device__ __nv_bfloat16 d_WqkvT_l[(size_t)QCOLS*DIM];
static __device__ __nv_bfloat16 d_WoutT_h[(size_t)DIM*DIM];
static __device__ __nv_bfloat16 d_WoutT_l[(size_t)DIM*DIM];

// ---------------- helpers ---------------------------------------------------
__device__ __forceinline__ uint32_t s2u(const void* p) {
    uint32_t a;
    asm("{ .reg .u64 t; cvta.to.shared.u64 t, %1; cvt.u32.u64 %0, t; }" : "=r"(a) : "l"(p));
    return a;
}
__device__ __forceinline__ void ldsm4(uint32_t& r0, uint32_t& r1, uint32_t& r2, uint32_t& r3,
                                      uint32_t addr) {
    asm volatile("ldmatrix.sync.aligned.m8n8.x4.shared.b16 {%0,%1,%2,%3}, [%4];"
                 : "=r"(r0), "=r"(r1), "=r"(r2), "=r"(r3) : "r"(addr));
}
__device__ __forceinline__ void mma_bf16(float* c, const uint32_t* a, const uint32_t* b) {
    asm volatile("mma.sync.aligned.m16n8k16.row.col.f32.bf16.bf16.f32 "
                 "{%0,%1,%2,%3}, {%4,%5,%6,%7}, {%8,%9}, {%0,%1,%2,%3};"
                 : "+f"(c[0]), "+f"(c[1]), "+f"(c[2]), "+f"(c[3])
                 : "r"(a[0]), "r"(a[1]), "r"(a[2]), "r"(a[3]), "r"(b[0]), "r"(b[1]));
}
__device__ __forceinline__ uint32_t pbf2(__nv_bfloat16 a, __nv_bfloat16 b) {
    __nv_bfloat162 t = __halves2bfloat162(a, b);
    return *reinterpret_cast<uint32_t*>(&t);
}

// ---- packed fp32x2 helpers for attention ----------------------------------
__device__ __forceinline__ unsigned long long pack2(float lo, float hi) {
    unsigned long long r;
    asm("mov.b64 %0, {%1, %2};" : "=l"(r) : "f"(lo), "f"(hi));
    return r;
}
__device__ __forceinline__ void unpack2(unsigned long long v, float& lo, float& hi) {
    asm("mov.b64 {%0, %1}, %2;" : "=f"(lo), "=f"(hi) : "l"(v));
}
__device__ __forceinline__ unsigned long long ffma2(unsigned long long a, unsigned long long b, unsigned long long c) {
    unsigned long long d;
    asm("fma.rn.f32x2 %0, %1, %2, %3;" : "=l"(d) : "l"(a), "l"(b), "l"(c));
    return d;
}
__device__ __forceinline__ unsigned long long fmul2(unsigned long long a, unsigned long long b) {
    unsigned long long d;
    asm("mul.rn.f32x2 %0, %1, %2;" : "=l"(d) : "l"(a), "l"(b));
    return d;
}

// ============================================================================
// Weight preprocessing: W [K=512][C] -> WT hi/lo bf16 [C][512]
// ============================================================================
template<bool QKV>
__global__ void transpose_split(const float* __restrict__ W) {
    const int C = QKV ? QCOLS : DIM;
    int idx = blockIdx.x * blockDim.x + threadIdx.x;
    if (idx < C * DIM) {
        int c = idx >> 9, k = idx & 511;
        float v = W[(size_t)k * C + c];
        __nv_bfloat16 h = __float2bfloat16_rn(v);
        __nv_bfloat16 l = __float2bfloat16_rn(v - __bfloat162float(h));
        if (QKV) { d_WqkvT_h[idx] = h; d_WqkvT_l[idx] = l; }
        else     { d_WoutT_h[idx] = h; d_WoutT_l[idx] = l; }
    }
}

// ============================================================================
// HMMA bf16 GEMM with 2-term compensation:  D = Ah*Bh + Ah*Bl + Al*Bh
// 128x128 tile, BK=32, 256 threads (8 warps, 2x4 grid, 64x32 per warp).
// Fragments loaded via ldmatrix.x4 (mapping cross-validated against the
// explicit per-thread LDS version that passed in R10).
// PROJ's A operand (d_O) is resolved IN DEVICE CODE (ATS host-shadow trap).
// ============================================================================
#define APAD 40                     // bf16 elems per smem row (32 + 8 pad)
#define SM_AH 0
#define SM_AL (128*APAD)
#define SM_BH (2*128*APAD)
#define SM_BL (3*128*APAD)
#define GEMM_DSMEM (128*132*4)      // 67584 (epilogue is the max user)

template<int NC, bool PROJ>
__global__ __launch_bounds__(256) void gemm_tc(
    const float* __restrict__ A, const float* __restrict__ bias, float* __restrict__ C)
{
    extern __shared__ __align__(16) char dyn[];
    __nv_bfloat16* sm16 = reinterpret_cast<__nv_bfloat16*>(dyn);

    const int tid  = threadIdx.x;
    const int wid  = tid >> 5;
    const int lane = tid & 31;
    const int wr   = wid >> 2;          // 0..1
    const int wc   = wid & 3;           // 0..3
    const int g    = lane >> 2;         // 0..7
    const int tg   = lane & 3;          // 0..3
    const int row0 = blockIdx.y * 128;
    const int col0 = blockIdx.x * 128;

    const float* __restrict__ Ap = PROJ ? (const float*)d_O : A;
    const __nv_bfloat16* __restrict__ BTh = PROJ ? d_WoutT_h : d_WqkvT_h;
    const __nv_bfloat16* __restrict__ BTl = PROJ ? d_WoutT_l : d_WqkvT_l;

    const uint32_t smb = s2u(sm16);

    float acc[4][4][4];
    #pragma unroll
    for (int i = 0; i < 4; i++)
        #pragma unroll
        for (int j = 0; j < 4; j++)
            #pragma unroll
            for (int e = 0; e < 4; e++) acc[i][j][e] = 0.f;

    // loader mapping: thread t -> row lr, k-half lh (16 elems each)
    const int lr = tid >> 1;
    const int lh = tid & 1;
    const int grA = row0 + lr;
    const bool okA = (grA < MROWS);
    const size_t aRow = (size_t)grA * DIM + lh * 16;
    const size_t bRow = (size_t)(col0 + lr) * DIM + lh * 16;

    float4 stA[4];
    uint4  stBh[2], stBl[2];

    auto load_regs = [&](int cc) {
        const int k0 = cc * 32;
        if (okA) {
            #pragma unroll
            for (int i = 0; i < 4; i++)
                stA[i] = *reinterpret_cast<const float4*>(&Ap[aRow + k0 + i * 4]);
        } else {
            #pragma unroll
            for (int i = 0; i < 4; i++) stA[i] = make_float4(0.f, 0.f, 0.f, 0.f);
        }
        stBh[0] = *reinterpret_cast<const uint4*>(&BTh[bRow + k0]);
        stBh[1] = *reinterpret_cast<const uint4*>(&BTh[bRow + k0 + 8]);
        stBl[0] = *reinterpret_cast<const uint4*>(&BTl[bRow + k0]);
        stBl[1] = *reinterpret_cast<const uint4*>(&BTl[bRow + k0 + 8]);
    };

    auto store_smem = [&]() {
        uint32_t hw[8], lw[8];
        #pragma unroll
        for (int i = 0; i < 4; i++) {
            float4 v = stA[i];
            __nv_bfloat16 h0 = __float2bfloat16_rn(v.x);
            __nv_bfloat16 h1 = __float2bfloat16_rn(v.y);
            __nv_bfloat16 h2 = __float2bfloat16_rn(v.z);
            __nv_bfloat16 h3 = __float2bfloat16_rn(v.w);
            hw[2*i]   = pbf2(h0, h1);
            hw[2*i+1] = pbf2(h2, h3);
            lw[2*i]   = pbf2(__float2bfloat16_rn(v.x - __bfloat162float(h0)),
                             __float2bfloat16_rn(v.y - __bfloat162float(h1)));
            lw[2*i+1] = pbf2(__float2bfloat16_rn(v.z - __bfloat162float(h2)),
                             __float2bfloat16_rn(v.w - __bfloat162float(h3)));
        }
        const int ao = lr * APAD + lh * 16;
        *reinterpret_cast<uint4*>(&sm16[SM_AH + ao])     = make_uint4(hw[0],hw[1],hw[2],hw[3]);
        *reinterpret_cast<uint4*>(&sm16[SM_AH + ao + 8]) = make_uint4(hw[4],hw[5],hw[6],hw[7]);
        *reinterpret_cast<uint4*>(&sm16[SM_AL + ao])     = make_uint4(lw[0],lw[1],lw[2],lw[3]);
        *reinterpret_cast<uint4*>(&sm16[SM_AL + ao + 8]) = make_uint4(lw[4],lw[5],lw[6],lw[7]);
        *reinterpret_cast<uint4*>(&sm16[SM_BH + ao])     = stBh[0];
        *reinterpret_cast<uint4*>(&sm16[SM_BH + ao + 8]) = stBh[1];
        *reinterpret_cast<uint4*>(&sm16[SM_BL + ao])     = stBl[0];
        *reinterpret_cast<uint4*>(&sm16[SM_BL + ao + 8]) = stBl[1];
    };

    // ldmatrix lane-address components (bf16-element units)
    const int aRowL = wr * 64 + (lane & 15);                       // + mt*16
    const int aColL = (lane >> 4) * 8;                             // + ks*16
    const int bRowL = wc * 32 + ((lane >> 4) << 3) + (lane & 7);   // + ntp*16
    const int bColL = ((lane >> 3) & 1) * 8;                       // + ks*16

    auto compute = [&]() {
        #pragma unroll
        for (int ks = 0; ks < 2; ks++) {
            uint32_t af[4][4], bf[2][4];
            const uint32_t aoff = (uint32_t)(ks * 16 + aColL) * 2;
            const uint32_t boff = (uint32_t)(ks * 16 + bColL) * 2;
            // ---- Ah x Bh ----
            #pragma unroll
            for (int mt = 0; mt < 4; mt++)
                ldsm4(af[mt][0], af[mt][1], af[mt][2], af[mt][3],
                      smb + (uint32_t)(SM_AH + (aRowL + mt * 16) * APAD) * 2 + aoff);
            #pragma unroll
            for (int ntp = 0; ntp < 2; ntp++)
                ldsm4(bf[ntp][0], bf[ntp][1], bf[ntp][2], bf[ntp][3],
                      smb + (uint32_t)(SM_BH + (bRowL + ntp * 16) * APAD) * 2 + boff);
            #pragma unroll
            for (int mt = 0; mt < 4; mt++)
                #pragma unroll
                for (int nt = 0; nt < 4; nt++)
                    mma_bf16(acc[mt][nt], af[mt], &bf[nt >> 1][(nt & 1) * 2]);
            // ---- Ah x Bl ----
            #pragma unroll
            for (int ntp = 0; ntp < 2; ntp++)
                ldsm4(bf[ntp][0], bf[ntp][1], bf[ntp][2], bf[ntp][3],
                      smb + (uint32_t)(SM_BL + (bRowL + ntp * 16) * APAD) * 2 + boff);
            #pragma unroll
            for (int mt = 0; mt < 4; mt++)
                #pragma unroll
                for (int nt = 0; nt < 4; nt++)
                    mma_bf16(acc[mt][nt], af[mt], &bf[nt >> 1][(nt & 1) * 2]);
            // ---- Al x Bh ----
            #pragma unroll
            for (int mt = 0; mt < 4; mt++)
                ldsm4(af[mt][0], af[mt][1], af[mt][2], af[mt][3],
                      smb + (uint32_t)(SM_AL + (aRowL + mt * 16) * APAD) * 2 + aoff);
            #pragma unroll
            for (int ntp = 0; ntp < 2; ntp++)
                ldsm4(bf[ntp][0], bf[ntp][1], bf[ntp][2], bf[ntp][3],
                      smb + (uint32_t)(SM_BH + (bRowL + ntp * 16) * APAD) * 2 + boff);
            #pragma unroll
            for (int mt = 0; mt < 4; mt++)
                #pragma unroll
                for (int nt = 0; nt < 4; nt++)
                    mma_bf16(acc[mt][nt], af[mt], &bf[nt >> 1][(nt & 1) * 2]);
        }
    };

    load_regs(0);
    store_smem();
    __syncthreads();
    #pragma unroll 1
    for (int cc = 0; cc < 16; cc++) {
        if (cc < 15) load_regs(cc + 1);
        compute();
        __syncthreads();
        if (cc < 15) { store_smem(); __syncthreads(); }
    }

    // ---- epilogue: fragments -> smem (stride 132) -> coalesced GMEM ----
    float* smemf = reinterpret_cast<float*>(dyn);
    #pragma unroll
    for (int mt = 0; mt < 4; mt++)
        #pragma unroll
        for (int nt = 0; nt < 4; nt++) {
            int r = wr * 64 + mt * 16 + g;
            int c = wc * 32 + nt * 8 + 2 * tg;
            *reinterpret_cast<float2*>(&smemf[r * 132 + c]) =
                make_float2(acc[mt][nt][0], acc[mt][nt][1]);
            *reinterpret_cast<float2*>(&smemf[(r + 8) * 132 + c]) =
                make_float2(acc[mt][nt][2], acc[mt][nt][3]);
        }
    __syncthreads();

    if (PROJ) {
        float4 bv = *reinterpret_cast<const float4*>(&bias[col0 + lane * 4]);
        #pragma unroll 4
        for (int it = 0; it < 16; it++) {
            int row = it * 8 + wid;
            int gr = row0 + row;
            if (gr < MROWS) {
                float4 v = *reinterpret_cast<const float4*>(&smemf[row * 132 + lane * 4]);
                v.x += bv.x; v.y += bv.y; v.z += bv.z; v.w += bv.w;
                *reinterpret_cast<float4*>(&C[(size_t)gr * DIM + col0 + lane * 4]) = v;
            }
        }
    } else {
        #pragma unroll 2
        for (int it = 0; it < 16; it++) {
            int row = it * 8 + wid;
            int gr = row0 + row;
            if (gr < MROWS) {
                int bb = gr / NTOT;
                int n  = gr - bb * NTOT;
                #pragma unroll
                for (int gg = 0; gg < 2; gg++) {
                    float2 v = *reinterpret_cast<const float2*>(
                        &smemf[row * 132 + gg * 64 + lane * 2]);
                    int cb = col0 + gg * 64;
                    int which = cb >> 9;
                    int h = (cb >> 6) & 7;
                    float* dst;
                    if (which == 0) { v.x *= SCALE; v.y *= SCALE; dst = d_Q; }
                    else if (which == 1) dst = d_Kb;
                    else                 dst = d_Vb;
                    *reinterpret_cast<float2*>(
                        &dst[(((size_t)bb * HH + h) * NTOT + n) * DH + lane * 2]) = v;
                }
            }
        }
    }
}

// ============================================================================
// cls attention, split-K: grid (32, 16). Block (bh, c) handles keys
// [c*197, min(3137,(c+1)*197)), writes partial {m, l, acc[64]}.
// ============================================================================
__global__ __launch_bounds__(256) void cls_part_kernel()
{
    __shared__ float s[CLS_KEYS];
    __shared__ __align__(16) float qv[DH];
    __shared__ float redA[8];
    __shared__ float outp[4][64];

    const int bh  = blockIdx.x;
    const int c   = blockIdx.y;
    const int tid = threadIdx.x;
    const int j0  = c * CLS_KEYS;
    const int cnt = min(CLS_KEYS, NTOT - j0);

    const float* __restrict__ Kp = d_Kb + ((size_t)bh * NTOT + j0) * DH;
    const float* __restrict__ Vp = d_Vb + ((size_t)bh * NTOT + j0) * DH;

    if (tid < DH) qv[tid] = d_Q[(size_t)bh * NTOT * DH + tid];
    __syncthreads();

    const unsigned long long* q2 = reinterpret_cast<const unsigned long long*>(qv);
    float lmax = -1e30f;
    for (int j = tid; j < cnt; j += 256) {
        const unsigned long long* kr =
            reinterpret_cast<const unsigned long long*>(Kp + (size_t)j * DH);
        unsigned long long dacc = 0ULL;
        #pragma unroll
        for (int t = 0; t < 32; t++) dacc = ffma2(q2[t], kr[t], dacc);
        float lo, hi; unpack2(dacc, lo, hi);
        float sv = lo + hi;
        s[j] = sv;
        lmax = fmaxf(lmax, sv);
    }
    #pragma unroll
    for (int o = 16; o; o >>= 1) lmax = fmaxf(lmax, __shfl_xor_sync(0xffffffffu, lmax, o));
    if ((tid & 31) == 0) redA[tid >> 5] = lmax;
    __syncthreads();
    float m = fmaxf(fmaxf(fmaxf(redA[0], redA[1]), fmaxf(redA[2], redA[3])),
                    fmaxf(fmaxf(redA[4], redA[5]), fmaxf(redA[6], redA[7])));
    __syncthreads();

    float lsum = 0.f;
    for (int j = tid; j < cnt; j += 256) {
        float p = __expf(s[j] - m);
        s[j] = p;
        lsum += p;
    }
    #pragma unroll
    for (int o = 16; o; o >>= 1) lsum += __shfl_xor_sync(0xffffffffu, lsum, o);
    if ((tid & 31) == 0) redA[tid >> 5] = lsum;
    __syncthreads();
    float l = redA[0] + redA[1] + redA[2] + redA[3] +
              redA[4] + redA[5] + redA[6] + redA[7];

    int d = tid & 63;
    int g = tid >> 6;
    float acc = 0.f;
    for (int j = g; j < cnt; j += 4)
        acc += s[j] * Vp[(size_t)j * DH + d];
    outp[g][d] = acc;
    __syncthreads();

    float* P = d_clsP + ((size_t)bh * CLS_CHUNKS + c) * 66;
    if (tid < 64)
        P[2 + tid] = outp[0][tid] + outp[1][tid] + outp[2][tid] + outp[3][tid];
    if (tid == 0) { P[0] = m; P[1] = l; }
}

// Combine 16 partials per (b,h): 32 blocks x 64 threads.
__global__ __launch_bounds__(64) void cls_reduce_kernel()
{
    const int bh  = blockIdx.x;
    const int d   = threadIdx.x;
    const float* P = d_clsP + (size_t)bh * CLS_CHUNKS * 66;

    float M = -1e30f;
    #pragma unroll
    for (int c = 0; c < CLS_CHUNKS; c++) M = fmaxf(M, P[c * 66]);
    float Z = 0.f, o = 0.f;
    #pragma unroll
    for (int c = 0; c < CLS_CHUNKS; c++) {
        float w = __expf(P[c * 66] - M);
        Z += P[c * 66 + 1] * w;
        o += P[c * 66 + 2 + d] * w;
    }
    int b = bh / HH, h = bh - b * HH;
    d_O[((size_t)b * NTOT + 0) * DIM + h * DH + d] = o / Z;
}

// ============================================================================
// Local attention: one block per (b,h,f). 196 queries, 197 keys (cls + 196).
// ============================================================================
__global__ __launch_bounds__(256) void local_attn_kernel()
{
    extern __shared__ __align__(16) float sm[];
    float* ks = sm;                  // 197*64
    float* vs = sm + 197 * 64;       // 197*64

    const int bhf = blockIdx.x;
    const int bh  = bhf >> 4;
    const int f   = bhf & 15;
    const size_t base = (size_t)bh * NTOT * DH;
    const int tid = threadIdx.x;

    const int TOTAL = 197 * 64;
    for (int i = tid; i < TOTAL; i += 256) {
        int r = i >> 6, d = i & 63;
        int n = (r == 0) ? 0 : (1 + f * NP + r - 1);
        ks[i] = d_Kb[base + (size_t)n * DH + d];
        vs[i] = d_Vb[base + (size_t)n * DH + d];
    }
    __syncthreads();

    if (tid < NP) {
        int nq = 1 + f * NP + tid;
        unsigned long long q2[32];
        const unsigned long long* qg =
            reinterpret_cast<const unsigned long long*>(d_Q + base + (size_t)nq * DH);
        #pragma unroll
        for (int t = 0; t < 32; t++) q2[t] = qg[t];

        const unsigned long long* k2 = reinterpret_cast<const unsigned long long*>(ks);
        const unsigned long long* v2 = reinterpret_cast<const unsigned long long*>(vs);

        float m = -1e30f, l = 0.f;
        unsigned long long acc[32];
        #pragma unroll
        for (int t = 0; t < 32; t++) acc[t] = 0ULL;

        for (int j = 0; j < 197; j++) {
            unsigned long long dacc = 0ULL;
            #pragma unroll
            for (int t = 0; t < 32; t++) dacc = ffma2(q2[t], k2[j * 32 + t], dacc);
            float lo, hi; unpack2(dacc, lo, hi);
            float sv = lo + hi;
            if (sv > m) {
                float c = __expf(m - sv);
                l *= c;
                unsigned long long c2 = pack2(c, c);
                #pragma unroll
                for (int t = 0; t < 32; t++) acc[t] = fmul2(acc[t], c2);
                m = sv;
            }
            float p = __expf(sv - m);
            l += p;
            unsigned long long p2 = pack2(p, p);
            #pragma unroll
            for (int t = 0; t < 32; t++) acc[t] = ffma2(p2, v2[j * 32 + t], acc[t]);
        }
        float inv = 1.0f / l;
        int b = bh / HH, h = bh - b * HH;
        float* op = d_O + ((size_t)b * NTOT + nq) * DIM + h * DH;
        #pragma unroll
        for (int t = 0; t < 32; t++) {
            float lo, hi; unpack2(acc[t], lo, hi);
            op[2 * t]     = lo * inv;
            op[2 * t + 1] = hi * inv;
        }
    }
}

// ============================================================================
extern "C" void kernel_launch(void* const* d_in, const int* in_sizes, int n_in,
                              void* d_out, int out_size)
{
    const float* x    = (const float*)d_in[0];
    const float* Wqkv = (const float*)d_in[1];
    const float* Wout = (const float*)d_in[2];
    const float* bout = (const float*)d_in[3];
    float* out = (float*)d_out;

    const int LOC_SMEM = 2 * 197 * 64 * (int)sizeof(float);   // 100864 B
    cudaFuncSetAttribute(local_attn_kernel,
                         cudaFuncAttributeMaxDynamicSharedMemorySize, LOC_SMEM);
    cudaFuncSetAttribute(gemm_tc<QCOLS, false>,
                         cudaFuncAttributeMaxDynamicSharedMemorySize, GEMM_DSMEM);
    cudaFuncSetAttribute(gemm_tc<DIM, true>,
                         cudaFuncAttributeMaxDynamicSharedMemorySize, GEMM_DSMEM);

    // 0) pre-split + transpose weights (bf16 hi/lo)
    transpose_split<true ><<<(QCOLS * DIM + 255) / 256, 256>>>(Wqkv);
    transpose_split<false><<<(DIM * DIM + 255) / 256, 256>>>(Wout);

    // 1) QKV GEMM (HMMA/ldmatrix) + scatter to Q/K/V (scaled Q)
    gemm_tc<QCOLS, false><<<dim3(QCOLS / 128, (MROWS + 127) / 128), 256, GEMM_DSMEM>>>(
        x, nullptr, nullptr);

    // 2) cls attention: split-K partials + combine
    cls_part_kernel<<<dim3(BHN, CLS_CHUNKS), 256>>>();
    cls_reduce_kernel<<<BHN, 64>>>();

    // 3) local attention
    local_attn_kernel<<<BB * HH * FF, 256, LOC_SMEM>>>();

    // 4) output projection (HMMA/ldmatrix) + bias — A = d_O resolved in device code
    gemm_tc<DIM, true><<<dim3(DIM / 128, (MROWS + 127) / 128), 256, GEMM_DSMEM>>>(
        nullptr, bout, out);
}